// round 15
// baseline (speedup 1.0000x reference)
#include <cuda_runtime.h>
#include <cstdint>

// Problem constants (fixed by the reference)
#define B_  2
#define S_  2048
#define D_  1024
#define H_  16
#define HD_ 64
#define BH  (B_*H_)            // 32
#define BSD ((long)B_*S_*D_)   // 4194304

// ---------------- scratch (static device globals; no allocation) ------------
__device__ float g_wt [4u*1024u*1024u];   // transposed weights [4][n][k] (tf32)
__device__ float g_qr [BSD];              // tf32-rounded query
__device__ float g_kr [BSD];              // tf32-rounded key
__device__ float g_vr [BSD];              // tf32-rounded value
__device__ float g_q  [BH * S_ * HD_];    // [b,h,s,hd] (tf32)
__device__ float g_k  [BH * S_ * HD_];    // [b,h,s,hd] (tf32)
__device__ float g_v  [BH * S_ * HD_];    // [b,h,s,hd] (tf32)
__device__ float g_ctx[B_ * S_ * D_];     // [b,s,d] (tf32)
__device__ float g_inv[BH * S_];          // 1 / softmax rowsum (f32)

// ---------------- helpers ---------------------------------------------------
__device__ __forceinline__ float f2tf(float f) {
    uint32_t u;
    asm("cvt.rna.tf32.f32 %0, %1;" : "=r"(u) : "f"(f));
    return __uint_as_float(u);
}

__device__ __forceinline__ uint32_t smem_u32(const void* p) {
    uint32_t a;
    asm("{ .reg .u64 t; cvta.to.shared.u64 t, %1; cvt.u32.u64 %0, t; }"
        : "=r"(a) : "l"(p));
    return a;
}

__device__ __forceinline__ void cp16(uint32_t dst, const float* src) {
    asm volatile("cp.async.cg.shared.global [%0], [%1], 16;\n"
                 :: "r"(dst), "l"(src));
}

#define CP_COMMIT() asm volatile("cp.async.commit_group;\n" ::: "memory")
#define CP_WAIT0()  asm volatile("cp.async.wait_group 0;\n" ::: "memory")

#define MMA_TF32(d, a0, a1, a2, a3, b0, b1)                                   \
    asm volatile(                                                             \
        "mma.sync.aligned.m16n8k8.row.col.f32.tf32.tf32.f32 "                 \
        "{%0,%1,%2,%3}, {%4,%5,%6,%7}, {%8,%9}, {%0,%1,%2,%3};\n"             \
        : "+f"((d)[0]), "+f"((d)[1]), "+f"((d)[2]), "+f"((d)[3])              \
        : "r"(a0), "r"(a1), "r"(a2), "r"(a3), "r"(b0), "r"(b1))

// ---------------- TF32 NT GEMM body: 128x256 tile, 8 warps of 64x64 ----------
// Operands must already be tf32-rounded in gmem; staging is cp.async.cg.
constexpr int SMA = 128 * 20;
constexpr int SMB = 256 * 20;
constexpr int GEMM_SMF = 2 * SMA + 2 * SMB + 128;
constexpr int GEMM_SMEMB = GEMM_SMF * 4;

template<int EPI>
__device__ __forceinline__ void gemm_body(
    float* sm_, const float* __restrict__ Ab, const float* __restrict__ Bb,
    const float* __restrict__ bias, float* __restrict__ C,
    const float* __restrict__ inv, int z, int m0, int n0, int K)
{
    float* sinv = sm_ + 2 * SMA + 2 * SMB;
    const uint32_t sb = smem_u32(sm_);

    const int tid  = threadIdx.x;
    const int lr = tid >> 2;
    const int lc = (tid & 3) << 2;
    const int warp = tid >> 5;
    const int lane = tid & 31;
    const int wm  = (warp >> 2) * 64;
    const int wn  = (warp & 3) * 64;
    const int gid = lane >> 2;
    const int tig = lane & 3;

    auto issue = [&](int kt, int buf) {
        const int k0 = kt * 16;
        const uint32_t ab = sb + (buf * SMA) * 4;
        const uint32_t bbs = sb + (2 * SMA + buf * SMB) * 4;
        #pragma unroll
        for (int i = 0; i < 2; i++) {
            int r = lr + i * 64;
            cp16(ab + (r * 20 + lc) * 4, Ab + (long)(m0 + r) * K + k0 + lc);
        }
        #pragma unroll
        for (int i = 0; i < 4; i++) {
            int r = lr + i * 64;
            cp16(bbs + (r * 20 + lc) * 4, Bb + (long)(n0 + r) * K + k0 + lc);
        }
        CP_COMMIT();
    };

    float acc[4][8][4] = {};
    auto compute = [&](int buf) {
        const float* Asb = sm_ + buf * SMA;
        const float* Bsb = sm_ + 2 * SMA + buf * SMB;
        #pragma unroll
        for (int kk = 0; kk < 2; kk++) {
            const int kb = kk * 8;
            uint32_t af[4][4], bf[8][2];
            #pragma unroll
            for (int mi = 0; mi < 4; mi++) {
                int r = wm + mi * 16 + gid;
                af[mi][0] = __float_as_uint(Asb[ r      * 20 + kb + tig    ]);
                af[mi][1] = __float_as_uint(Asb[(r + 8) * 20 + kb + tig    ]);
                af[mi][2] = __float_as_uint(Asb[ r      * 20 + kb + tig + 4]);
                af[mi][3] = __float_as_uint(Asb[(r + 8) * 20 + kb + tig + 4]);
            }
            #pragma unroll
            for (int ni = 0; ni < 8; ni++) {
                int r = wn + ni * 8 + gid;
                bf[ni][0] = __float_as_uint(Bsb[r * 20 + kb + tig    ]);
                bf[ni][1] = __float_as_uint(Bsb[r * 20 + kb + tig + 4]);
            }
            #pragma unroll
            for (int mi = 0; mi < 4; mi++)
                #pragma unroll
                for (int ni = 0; ni < 8; ni++)
                    MMA_TF32(acc[mi][ni], af[mi][0], af[mi][1], af[mi][2],
                             af[mi][3], bf[ni][0], bf[ni][1]);
        }
    };

    if (EPI == 2 && tid < 128)
        sinv[tid] = inv[(long)z * 2048 + m0 + tid];

    const int NT = K >> 4;
    issue(0, 0);
    int buf = 0;
    for (int kt = 0; kt < NT; kt++) {
        CP_WAIT0();
        __syncthreads();
        if (kt + 1 < NT) issue(kt + 1, buf ^ 1);
        compute(buf);
        buf ^= 1;
    }

    #pragma unroll
    for (int mi = 0; mi < 4; mi++) {
        #pragma unroll
        for (int ni = 0; ni < 8; ni++) {
            int lrow = wm + mi * 16 + gid;
            int m = m0 + lrow;
            int n = n0 + wn + ni * 8 + tig * 2;
            float a0 = acc[mi][ni][0], a1 = acc[mi][ni][1];
            float a2 = acc[mi][ni][2], a3 = acc[mi][ni][3];
            if constexpr (EPI == 0) {
                int b = m >> 11, s = m & 2047, h = n >> 6, hd = n & 63;
                long base = (long)((b * 16 + h) * 2048 + s) * 64 + hd;
                float b0 = bias[n], b1 = bias[n + 1];
                *(float2*)(C + base)       = make_float2(f2tf(a0 + b0), f2tf(a1 + b1));
                *(float2*)(C + base + 512) = make_float2(f2tf(a2 + b0), f2tf(a3 + b1));
            } else if constexpr (EPI == 2) {
                float s0 = sinv[lrow], s1 = sinv[lrow + 8];
                float e0 = __expf(a0 * 0.125f) * s0;
                float e1 = __expf(a1 * 0.125f) * s0;
                float e2 = __expf(a2 * 0.125f) * s1;
                float e3 = __expf(a3 * 0.125f) * s1;
                long base = (long)z * (2048L * 2048) + (long)m * 2048 + n;
                __stcs((float2*)(C + base),            make_float2(e0, e1));
                __stcs((float2*)(C + base + 8 * 2048), make_float2(e2, e3));
            } else {
                long base = (long)m * 1024 + n;
                float b0 = bias[n], b1 = bias[n + 1];
                *(float2*)(C + base)            = make_float2(a0 + b0, a1 + b1);
                *(float2*)(C + base + 8 * 1024) = make_float2(a2 + b0, a3 + b1);
            }
        }
    }
}

// ---------------- fused Q/K/V projection (grid.z selects) --------------------
__global__ void __launch_bounds__(256)
qkv_proj(const float* __restrict__ q, const float* __restrict__ k,
         const float* __restrict__ v, const float* __restrict__ wt,
         const float* __restrict__ bq, const float* __restrict__ bk,
         const float* __restrict__ bv,
         float* __restrict__ gq, float* __restrict__ gk, float* __restrict__ gv)
{
    extern __shared__ float sm_[];
    const int z = blockIdx.z;
    const float* A    = (z == 0) ? q  : (z == 1) ? k  : v;
    const float* bias = (z == 0) ? bq : (z == 1) ? bk : bv;
    float*       C    = (z == 0) ? gq : (z == 1) ? gk : gv;
    gemm_body<0>(sm_, A, wt + (long)z * 1024 * 1024, bias, C, nullptr, 0,
                 blockIdx.y * 128, blockIdx.x * 256, 1024);
}

// ---------------- merged pass2 (attn write) + output projection --------------
__global__ void __launch_bounds__(256)
attn_out_combo(const float* __restrict__ qh, const float* __restrict__ kh,
               const float* __restrict__ vinv, float* __restrict__ attn,
               const float* __restrict__ ctx, const float* __restrict__ wo_t,
               const float* __restrict__ bo, float* __restrict__ out)
{
    extern __shared__ float sm_[];
    const int bid = blockIdx.x;
    if (bid < 128) {
        int m0 = (bid >> 2) * 128;
        int n0 = (bid & 3) * 256;
        gemm_body<4>(sm_, ctx, wo_t, bo, out, nullptr, 0, m0, n0, 1024);
    } else {
        int t  = bid - 128;
        int z  = t >> 7;
        int m0 = ((t >> 3) & 15) * 128;
        int n0 = (t & 7) * 256;
        gemm_body<2>(sm_, qh + (long)z * S_ * HD_, kh + (long)z * S_ * HD_,
                     nullptr, attn, vinv, z, m0, n0, 64);
    }
}

// ---------------- flash pass1: 64-query tiles, 2 CTAs/SM ---------------------
// Per block: one (b,h), 64 query rows. 8 warps as 4x2 grid of 16x32 warp
// tiles. K/V (64-key tiles) double-buffered with register prefetch.
// smem ~105 KB -> 2 CTAs/SM; cross-CTA overlap hides the serial
// S-MMA -> exp -> P -> PV-MMA chain. Per-row math identical to the 128-row
// version (same K-tile order) -> bit-identical results.
__global__ void __launch_bounds__(256, 2)
flash_ctx(const float* __restrict__ gq, const float* __restrict__ gk,
          const float* __restrict__ gv, float* __restrict__ ctx,
          float* __restrict__ ginv)
{
    extern __shared__ float sm[];
    float* Qs   = sm;                   // 64*68 = 4352
    float* Ks   = Qs + 64 * 68;         // 2 stages * 64*68
    float* Vs   = Ks + 2 * 64 * 68;     // 2 stages * 64*68  ([hd][key])
    float* Ps   = Vs + 2 * 64 * 68;     // 64*68
    float* ssum = Ps + 64 * 68;         // 128
    float* sinv = ssum + 128;           // 64

    const int tid  = threadIdx.x;
    const int z    = blockIdx.z;
    const int m0   = blockIdx.y * 64;
    const int warp = tid >> 5, lane = tid & 31;
    const int wm   = (warp >> 1) * 16;  // 4 row groups of 16 queries
    const int colg = warp & 1;
    const int wn   = colg * 32;         // 2 col groups of 32 keys/hd
    const int gid  = lane >> 2, tig = lane & 3;

    // Q tile once (64x64)
    {
        const float* q = gq + ((long)z * 2048 + m0) * 64;
        #pragma unroll
        for (int s = 0; s < 4; s++) {
            int fi = tid + s * 256;
            int r = fi >> 4, c = (fi & 15) << 2;
            float4 v = *reinterpret_cast<const float4*>(q + r * 64 + c);
            float* p = &Qs[r * 68 + c];
            p[0] = f2tf(v.x); p[1] = f2tf(v.y);
            p[2] = f2tf(v.z); p[3] = f2tf(v.w);
        }
    }

    float4 pk[4], pv[4];
    auto ldg_kv = [&](int j) {
        const long base = ((long)z * 2048 + j * 64) * 64;
        #pragma unroll
        for (int s = 0; s < 4; s++) {
            int fi = tid + s * 256;
            int r = fi >> 4, c = (fi & 15) << 2;
            pk[s] = *reinterpret_cast<const float4*>(gk + base + r * 64 + c);
            pv[s] = *reinterpret_cast<const float4*>(gv + base + r * 64 + c);
        }
    };
    auto sts_kv = [&](int b) {
        float* Ksb = Ks + b * (64 * 68);
        float* Vsb = Vs + b * (64 * 68);
        #pragma unroll
        for (int s = 0; s < 4; s++) {
            int fi = tid + s * 256;
            int r = fi >> 4, c = (fi & 15) << 2;   // r=key, c=hd
            float* p = &Ksb[r * 68 + c];
            p[0] = f2tf(pk[s].x); p[1] = f2tf(pk[s].y);
            p[2] = f2tf(pk[s].z); p[3] = f2tf(pk[s].w);
            Vsb[(c + 0) * 68 + r] = f2tf(pv[s].x);
            Vsb[(c + 1) * 68 + r] = f2tf(pv[s].y);
            Vsb[(c + 2) * 68 + r] = f2tf(pv[s].z);
            Vsb[(c + 3) * 68 + r] = f2tf(pv[s].w);
        }
    };

    float acc[4][4] = {};               // ctx accumulator [ni][reg]
    float rsum[2] = {0.f, 0.f};

    ldg_kv(0);
    sts_kv(0);
    __syncthreads();
    int buf = 0;

    for (int j = 0; j < 32; j++) {
        if (j < 31) ldg_kv(j + 1);      // prefetch; hidden under S-MMA

        // S = Q[16x64] @ K_j[32x64]^T per warp
        float* Ksb = Ks + buf * (64 * 68);
        float sa[4][4] = {};
        #pragma unroll
        for (int kc = 0; kc < 8; kc++) {
            const int kb = kc * 8;
            uint32_t af[4], bf[4][2];
            af[0] = __float_as_uint(Qs[(wm + gid)     * 68 + kb + tig    ]);
            af[1] = __float_as_uint(Qs[(wm + 8 + gid) * 68 + kb + tig    ]);
            af[2] = __float_as_uint(Qs[(wm + gid)     * 68 + kb + tig + 4]);
            af[3] = __float_as_uint(Qs[(wm + 8 + gid) * 68 + kb + tig + 4]);
            #pragma unroll
            for (int ni = 0; ni < 4; ni++) {
                int r = wn + ni * 8 + gid;
                bf[ni][0] = __float_as_uint(Ksb[r * 68 + kb + tig    ]);
                bf[ni][1] = __float_as_uint(Ksb[r * 68 + kb + tig + 4]);
            }
            #pragma unroll
            for (int ni = 0; ni < 4; ni++)
                MMA_TF32(sa[ni], af[0], af[1], af[2], af[3],
                         bf[ni][0], bf[ni][1]);
        }

        // exp -> P (smem tf32), accumulate rowsums
        {
            int r0 = wm + gid;
            #pragma unroll
            for (int ni = 0; ni < 4; ni++) {
                int c = wn + ni * 8 + tig * 2;
                float e0 = __expf(sa[ni][0] * 0.125f);
                float e1 = __expf(sa[ni][1] * 0.125f);
                float e2 = __expf(sa[ni][2] * 0.125f);
                float e3 = __expf(sa[ni][3] * 0.125f);
                Ps[ r0      * 68 + c    ] = f2tf(e0);
                Ps[ r0      * 68 + c + 1] = f2tf(e1);
                Ps[(r0 + 8) * 68 + c    ] = f2tf(e2);
                Ps[(r0 + 8) * 68 + c + 1] = f2tf(e3);
                rsum[0] += e0 + e1;
                rsum[1] += e2 + e3;
            }
        }
        __syncthreads();                // Ps complete across both col groups

        if (j < 31) sts_kv(buf ^ 1);    // stage next tile into idle buffer

        // ctx += P[16x64] @ V_j  (Vs is [hd][key] -> NT B operand)
        float* Vsb = Vs + buf * (64 * 68);
        #pragma unroll
        for (int kc = 0; kc < 8; kc++) {
            const int kb = kc * 8;
            uint32_t af[4], bf[4][2];
            af[0] = __float_as_uint(Ps[(wm + gid)     * 68 + kb + tig    ]);
            af[1] = __float_as_uint(Ps[(wm + 8 + gid) * 68 + kb + tig    ]);
            af[2] = __float_as_uint(Ps[(wm + gid)     * 68 + kb + tig + 4]);
            af[3] = __float_as_uint(Ps[(wm + 8 + gid) * 68 + kb + tig + 4]);
            #pragma unroll
            for (int ni = 0; ni < 4; ni++) {
                int r = wn + ni * 8 + gid;
                bf[ni][0] = __float_as_uint(Vsb[r * 68 + kb + tig    ]);
                bf[ni][1] = __float_as_uint(Vsb[r * 68 + kb + tig + 4]);
            }
            #pragma unroll
            for (int ni = 0; ni < 4; ni++)
                MMA_TF32(acc[ni], af[0], af[1], af[2], af[3],
                         bf[ni][0], bf[ni][1]);
        }
        __syncthreads();                // next stage staged; Ps reusable
        buf ^= 1;
    }

    // ---- reduce rowsums (tig quad, then across the 2 col groups) ----
    #pragma unroll
    for (int i = 0; i < 2; i++) {
        rsum[i] += __shfl_xor_sync(0xffffffffu, rsum[i], 1);
        rsum[i] += __shfl_xor_sync(0xffffffffu, rsum[i], 2);
    }
    if (tig == 0) {
        ssum[(wm + gid)     * 2 + colg] = rsum[0];
        ssum[(wm + 8 + gid) * 2 + colg] = rsum[1];
    }
    __syncthreads();
    if (tid < 64) {
        float v = 1.0f / (ssum[tid * 2] + ssum[tid * 2 + 1]);
        sinv[tid] = v;
        ginv[(long)z * 2048 + m0 + tid] = v;
    }
    __syncthreads();

    // ---- write normalized ctx (tf32-rounded; consumed by out-proj) ----
    const int b = z >> 4, h = z & 15;
    {
        int r0 = wm + gid;
        float s0 = sinv[r0], s1 = sinv[r0 + 8];
        #pragma unroll
        for (int ni = 0; ni < 4; ni++) {
            int c = wn + ni * 8 + tig * 2;
            long base = ((long)(b * 2048 + m0 + r0) << 10) + h * 64 + c;
            *(float2*)(ctx + base) =
                make_float2(f2tf(acc[ni][0] * s0), f2tf(acc[ni][1] * s0));
            *(float2*)(ctx + base + (8L << 10)) =
                make_float2(f2tf(acc[ni][2] * s1), f2tf(acc[ni][3] * s1));
        }
    }
}

// ---------------- tf32 pre-round of the three inputs -------------------------
__global__ void __launch_bounds__(256)
round3(const float* __restrict__ q, const float* __restrict__ k,
       const float* __restrict__ v, float* __restrict__ oq,
       float* __restrict__ ok, float* __restrict__ ov)
{
    const int z = blockIdx.y;
    const float* src = (z == 0) ? q  : (z == 1) ? k  : v;
    float*       dst = (z == 0) ? oq : (z == 1) ? ok : ov;
    long i = (long)blockIdx.x * 256 + threadIdx.x;
    float4 a = reinterpret_cast<const float4*>(src)[i];
    a.x = f2tf(a.x); a.y = f2tf(a.y); a.z = f2tf(a.z); a.w = f2tf(a.w);
    reinterpret_cast<float4*>(dst)[i] = a;
}

// ---------------- fused 4x 1024x1024 weight transpose (tf32 out) -------------
__global__ void __launch_bounds__(256)
transpose4(const float* __restrict__ w0, const float* __restrict__ w1,
           const float* __restrict__ w2, const float* __restrict__ w3,
           float* __restrict__ out)
{
    __shared__ float t[32][33];
    const int z = blockIdx.z;
    const float* in = (z == 0) ? w0 : (z == 1) ? w1 : (z == 2) ? w2 : w3;
    float* o = out + (long)z * 1024 * 1024;
    int tx = threadIdx.x, ty = threadIdx.y;
    int x  = blockIdx.x * 32 + tx;
    #pragma unroll
    for (int i = ty; i < 32; i += 8)
        t[i][tx] = in[(long)(blockIdx.y * 32 + i) * 1024 + x];
    __syncthreads();
    int xo = blockIdx.y * 32 + tx;
    #pragma unroll
    for (int i = ty; i < 32; i += 8)
        o[(long)(blockIdx.x * 32 + i) * 1024 + xo] = f2tf(t[tx][i]);
}

// ---------------- launch ------------------------------------------------------
extern "C" void kernel_launch(void* const* d_in, const int* in_sizes, int n_in,
                              void* d_out, int out_size)
{
    const float* query = (const float*)d_in[0];
    const float* key   = (const float*)d_in[1];
    const float* value = (const float*)d_in[2];
    const float* Wq    = (const float*)d_in[3];
    const float* bq    = (const float*)d_in[4];
    const float* Wk    = (const float*)d_in[5];
    const float* bk    = (const float*)d_in[6];
    const float* Wv    = (const float*)d_in[7];
    const float* bv    = (const float*)d_in[8];
    const float* Wo    = (const float*)d_in[9];
    const float* bo    = (const float*)d_in[10];

    float* out  = (float*)d_out;
    float* attn = out + BSD;             // outputs concatenated: (out, attn)

    void* p;
    cudaGetSymbolAddress(&p, g_wt);  float* wt   = (float*)p;
    cudaGetSymbolAddress(&p, g_qr);  float* qr   = (float*)p;
    cudaGetSymbolAddress(&p, g_kr);  float* kr   = (float*)p;
    cudaGetSymbolAddress(&p, g_vr);  float* vr   = (float*)p;
    cudaGetSymbolAddress(&p, g_q);   float* qh   = (float*)p;
    cudaGetSymbolAddress(&p, g_k);   float* kh   = (float*)p;
    cudaGetSymbolAddress(&p, g_v);   float* vh   = (float*)p;
    cudaGetSymbolAddress(&p, g_ctx); float* ctx  = (float*)p;
    cudaGetSymbolAddress(&p, g_inv); float* vinv = (float*)p;

    const int FLASH_SMEM =
        (64*68 + 2*64*68 + 2*64*68 + 64*68 + 128 + 64) * 4;   // 105216 B
    static int smem_set = 0;
    if (!smem_set) {
        cudaFuncSetAttribute(flash_ctx,
                             cudaFuncAttributeMaxDynamicSharedMemorySize,
                             FLASH_SMEM);
        cudaFuncSetAttribute(qkv_proj,
                             cudaFuncAttributeMaxDynamicSharedMemorySize,
                             GEMM_SMEMB);
        cudaFuncSetAttribute(attn_out_combo,
                             cudaFuncAttributeMaxDynamicSharedMemorySize,
                             GEMM_SMEMB);
        smem_set = 1;
    }

    const long WS = 1024L * 1024L;

    // 1) tf32-round the three inputs
    round3<<<dim3(4096, 3), 256>>>(query, key, value, qr, kr, vr);

    // 2) all four weight transposes (tf32 out)
    transpose4<<<dim3(32, 32, 4), dim3(32, 8)>>>(Wq, Wk, Wv, Wo, wt);

    // 3) fused Q/K/V projections (cp.async staging, 64x64 warp tiles)
    qkv_proj<<<dim3(4, 32, 3), 256, GEMM_SMEMB>>>(qr, kr, vr, wt,
                                                  bq, bk, bv, qh, kh, vh);

    // 4) fused scores->softmax-sum->ctx; 64-query tiles, 2 CTAs/SM
    flash_ctx<<<dim3(1, 32, BH), 256, FLASH_SMEM>>>(qh, kh, vh, ctx, vinv);

    // 5) merged: out-projection (first) + normalized attn write
    attn_out_combo<<<128 + 4096, 256, GEMM_SMEMB>>>(qh, kh, vinv, attn,
                                                    ctx, wt + 3 * WS, bo, out);
}

// round 16
// speedup vs baseline: 1.1230x; 1.1230x over previous
#include <cuda_runtime.h>
#include <cstdint>

// Problem constants (fixed by the reference)
#define B_  2
#define S_  2048
#define D_  1024
#define H_  16
#define HD_ 64
#define BH  (B_*H_)            // 32
#define BSD ((long)B_*S_*D_)   // 4194304

// ---------------- scratch (static device globals; no allocation) ------------
__device__ float g_wt [4u*1024u*1024u];   // transposed weights [4][n][k] (tf32)
__device__ float g_qr [BSD];              // tf32-rounded query
__device__ float g_kr [BSD];              // tf32-rounded key
__device__ float g_vr [BSD];              // tf32-rounded value
__device__ float g_q  [BH * S_ * HD_];    // [b,h,s,hd] (tf32)
__device__ float g_k  [BH * S_ * HD_];    // [b,h,s,hd] (tf32)
__device__ float g_v  [BH * S_ * HD_];    // [b,h,s,hd] (tf32)
__device__ float g_ctx[B_ * S_ * D_];     // [b,s,d] (tf32)
__device__ float g_inv[BH * S_];          // 1 / softmax rowsum (f32)

// ---------------- helpers ---------------------------------------------------
__device__ __forceinline__ float f2tf(float f) {
    uint32_t u;
    asm("cvt.rna.tf32.f32 %0, %1;" : "=r"(u) : "f"(f));
    return __uint_as_float(u);
}

__device__ __forceinline__ uint32_t smem_u32(const void* p) {
    uint32_t a;
    asm("{ .reg .u64 t; cvta.to.shared.u64 t, %1; cvt.u32.u64 %0, t; }"
        : "=r"(a) : "l"(p));
    return a;
}

__device__ __forceinline__ void cp16(uint32_t dst, const float* src) {
    asm volatile("cp.async.cg.shared.global [%0], [%1], 16;\n"
                 :: "r"(dst), "l"(src));
}

#define CP_COMMIT() asm volatile("cp.async.commit_group;\n" ::: "memory")
#define CP_WAIT0()  asm volatile("cp.async.wait_group 0;\n" ::: "memory")

#define MMA_TF32(d, a0, a1, a2, a3, b0, b1)                                   \
    asm volatile(                                                             \
        "mma.sync.aligned.m16n8k8.row.col.f32.tf32.tf32.f32 "                 \
        "{%0,%1,%2,%3}, {%4,%5,%6,%7}, {%8,%9}, {%0,%1,%2,%3};\n"             \
        : "+f"((d)[0]), "+f"((d)[1]), "+f"((d)[2]), "+f"((d)[3])              \
        : "r"(a0), "r"(a1), "r"(a2), "r"(a3), "r"(b0), "r"(b1))

// ---------------- TF32 NT GEMM body: 128x256 tile, 8 warps of 64x64 ----------
// Operands must already be tf32-rounded in gmem; staging is cp.async.cg.
constexpr int SMA = 128 * 20;
constexpr int SMB = 256 * 20;
constexpr int GEMM_SMF = 2 * SMA + 2 * SMB + 128;
constexpr int GEMM_SMEMB = GEMM_SMF * 4;

template<int EPI>
__device__ __forceinline__ void gemm_body(
    float* sm_, const float* __restrict__ Ab, const float* __restrict__ Bb,
    const float* __restrict__ bias, float* __restrict__ C,
    const float* __restrict__ inv, int z, int m0, int n0, int K)
{
    float* sinv = sm_ + 2 * SMA + 2 * SMB;
    const uint32_t sb = smem_u32(sm_);

    const int tid  = threadIdx.x;
    const int lr = tid >> 2;
    const int lc = (tid & 3) << 2;
    const int warp = tid >> 5;
    const int lane = tid & 31;
    const int wm  = (warp >> 2) * 64;
    const int wn  = (warp & 3) * 64;
    const int gid = lane >> 2;
    const int tig = lane & 3;

    auto issue = [&](int kt, int buf) {
        const int k0 = kt * 16;
        const uint32_t ab = sb + (buf * SMA) * 4;
        const uint32_t bbs = sb + (2 * SMA + buf * SMB) * 4;
        #pragma unroll
        for (int i = 0; i < 2; i++) {
            int r = lr + i * 64;
            cp16(ab + (r * 20 + lc) * 4, Ab + (long)(m0 + r) * K + k0 + lc);
        }
        #pragma unroll
        for (int i = 0; i < 4; i++) {
            int r = lr + i * 64;
            cp16(bbs + (r * 20 + lc) * 4, Bb + (long)(n0 + r) * K + k0 + lc);
        }
        CP_COMMIT();
    };

    float acc[4][8][4] = {};
    auto compute = [&](int buf) {
        const float* Asb = sm_ + buf * SMA;
        const float* Bsb = sm_ + 2 * SMA + buf * SMB;
        #pragma unroll
        for (int kk = 0; kk < 2; kk++) {
            const int kb = kk * 8;
            uint32_t af[4][4], bf[8][2];
            #pragma unroll
            for (int mi = 0; mi < 4; mi++) {
                int r = wm + mi * 16 + gid;
                af[mi][0] = __float_as_uint(Asb[ r      * 20 + kb + tig    ]);
                af[mi][1] = __float_as_uint(Asb[(r + 8) * 20 + kb + tig    ]);
                af[mi][2] = __float_as_uint(Asb[ r      * 20 + kb + tig + 4]);
                af[mi][3] = __float_as_uint(Asb[(r + 8) * 20 + kb + tig + 4]);
            }
            #pragma unroll
            for (int ni = 0; ni < 8; ni++) {
                int r = wn + ni * 8 + gid;
                bf[ni][0] = __float_as_uint(Bsb[r * 20 + kb + tig    ]);
                bf[ni][1] = __float_as_uint(Bsb[r * 20 + kb + tig + 4]);
            }
            #pragma unroll
            for (int mi = 0; mi < 4; mi++)
                #pragma unroll
                for (int ni = 0; ni < 8; ni++)
                    MMA_TF32(acc[mi][ni], af[mi][0], af[mi][1], af[mi][2],
                             af[mi][3], bf[ni][0], bf[ni][1]);
        }
    };

    if (EPI == 2 && tid < 128)
        sinv[tid] = inv[(long)z * 2048 + m0 + tid];

    const int NT = K >> 4;
    issue(0, 0);
    int buf = 0;
    for (int kt = 0; kt < NT; kt++) {
        CP_WAIT0();
        __syncthreads();
        if (kt + 1 < NT) issue(kt + 1, buf ^ 1);
        compute(buf);
        buf ^= 1;
    }

    #pragma unroll
    for (int mi = 0; mi < 4; mi++) {
        #pragma unroll
        for (int ni = 0; ni < 8; ni++) {
            int lrow = wm + mi * 16 + gid;
            int m = m0 + lrow;
            int n = n0 + wn + ni * 8 + tig * 2;
            float a0 = acc[mi][ni][0], a1 = acc[mi][ni][1];
            float a2 = acc[mi][ni][2], a3 = acc[mi][ni][3];
            if constexpr (EPI == 0) {
                int b = m >> 11, s = m & 2047, h = n >> 6, hd = n & 63;
                long base = (long)((b * 16 + h) * 2048 + s) * 64 + hd;
                float b0 = bias[n], b1 = bias[n + 1];
                *(float2*)(C + base)       = make_float2(f2tf(a0 + b0), f2tf(a1 + b1));
                *(float2*)(C + base + 512) = make_float2(f2tf(a2 + b0), f2tf(a3 + b1));
            } else if constexpr (EPI == 2) {
                float s0 = sinv[lrow], s1 = sinv[lrow + 8];
                float e0 = __expf(a0 * 0.125f) * s0;
                float e1 = __expf(a1 * 0.125f) * s0;
                float e2 = __expf(a2 * 0.125f) * s1;
                float e3 = __expf(a3 * 0.125f) * s1;
                long base = (long)z * (2048L * 2048) + (long)m * 2048 + n;
                __stcs((float2*)(C + base),            make_float2(e0, e1));
                __stcs((float2*)(C + base + 8 * 2048), make_float2(e2, e3));
            } else {
                long base = (long)m * 1024 + n;
                float b0 = bias[n], b1 = bias[n + 1];
                *(float2*)(C + base)            = make_float2(a0 + b0, a1 + b1);
                *(float2*)(C + base + 8 * 1024) = make_float2(a2 + b0, a3 + b1);
            }
        }
    }
}

// ---------------- fused Q/K/V projection (grid.z selects) --------------------
__global__ void __launch_bounds__(256)
qkv_proj(const float* __restrict__ q, const float* __restrict__ k,
         const float* __restrict__ v, const float* __restrict__ wt,
         const float* __restrict__ bq, const float* __restrict__ bk,
         const float* __restrict__ bv,
         float* __restrict__ gq, float* __restrict__ gk, float* __restrict__ gv)
{
    extern __shared__ float sm_[];
    const int z = blockIdx.z;
    const float* A    = (z == 0) ? q  : (z == 1) ? k  : v;
    const float* bias = (z == 0) ? bq : (z == 1) ? bk : bv;
    float*       C    = (z == 0) ? gq : (z == 1) ? gk : gv;
    gemm_body<0>(sm_, A, wt + (long)z * 1024 * 1024, bias, C, nullptr, 0,
                 blockIdx.y * 128, blockIdx.x * 256, 1024);
}

// ---------------- merged pass2 (attn write) + output projection --------------
__global__ void __launch_bounds__(256)
attn_out_combo(const float* __restrict__ qh, const float* __restrict__ kh,
               const float* __restrict__ vinv, float* __restrict__ attn,
               const float* __restrict__ ctx, const float* __restrict__ wo_t,
               const float* __restrict__ bo, float* __restrict__ out)
{
    extern __shared__ float sm_[];
    const int bid = blockIdx.x;
    if (bid < 128) {
        int m0 = (bid >> 2) * 128;
        int n0 = (bid & 3) * 256;
        gemm_body<4>(sm_, ctx, wo_t, bo, out, nullptr, 0, m0, n0, 1024);
    } else {
        int t  = bid - 128;
        int z  = t >> 7;
        int m0 = ((t >> 3) & 15) * 128;
        int n0 = (t & 7) * 256;
        gemm_body<2>(sm_, qh + (long)z * S_ * HD_, kh + (long)z * S_ * HD_,
                     nullptr, attn, vinv, z, m0, n0, 64);
    }
}

// ---------------- flash pass1: 128-q tile, single-buffered K/V, 2 CTAs/SM ----
// R13's layout (8 warps of 32x32, best per-thread smem traffic) but smem cut
// to ~104 KB (single K/V stage) so TWO independent CTAs co-reside per SM and
// hide each other's LDG/exp/barrier latency (DRAM is ~idle, so the lost
// double-buffering costs only latency, which the sibling CTA covers).
// K and Q staged via cp.async (values already tf32 in gmem); V needs the
// [hd][key] transpose so it keeps LDG+STS. Math order per row identical to
// R13 -> bit-identical results.
__global__ void __launch_bounds__(256, 2)
flash_ctx(const float* __restrict__ gq, const float* __restrict__ gk,
          const float* __restrict__ gv, float* __restrict__ ctx,
          float* __restrict__ ginv)
{
    extern __shared__ float sm[];
    float* Qs   = sm;                   // 128*68 = 8704
    float* Ks   = Qs + 128 * 68;        // 64*68  = 4352
    float* Vs   = Ks + 64 * 68;         // 64*68  = 4352  ([hd][key])
    float* Ps   = Vs + 64 * 68;         // 128*68 = 8704
    float* ssum = Ps + 128 * 68;        // 256
    float* sinv = ssum + 256;           // 128

    const uint32_t sb = smem_u32(sm);
    const int tid  = threadIdx.x;
    const int z    = blockIdx.z;
    const int m0   = blockIdx.y * 128;
    const int warp = tid >> 5, lane = tid & 31;
    const int wm   = (warp >> 1) * 32;
    const int wn   = (warp & 1) * 32;
    const int colg = warp & 1;
    const int gid  = lane >> 2, tig = lane & 3;

    // Q tile once via cp.async (gq already tf32)
    {
        const float* q = gq + ((long)z * 2048 + m0) * 64;
        #pragma unroll
        for (int s = 0; s < 8; s++) {
            int fi = tid + s * 256;
            int r = fi >> 4, c = (fi & 15) << 2;
            cp16(sb + (r * 68 + c) * 4, q + r * 64 + c);
        }
        CP_COMMIT();
    }

    float acc[2][4][4] = {};
    float rsum[4] = {0.f, 0.f, 0.f, 0.f};

    for (int j = 0; j < 32; j++) {
        __syncthreads();                // prev S/PV reads of Ks/Vs done
        const long base = ((long)z * 2048 + j * 64) * 64;
        // K: cp.async straight into smem (row-major matches, already tf32)
        #pragma unroll
        for (int s = 0; s < 4; s++) {
            int fi = tid + s * 256;
            int r = fi >> 4, c = (fi & 15) << 2;
            cp16(sb + (128 * 68 + r * 68 + c) * 4, gk + base + r * 64 + c);
        }
        CP_COMMIT();
        // V: transpose to [hd][key] (already tf32 -> plain stores)
        #pragma unroll
        for (int s = 0; s < 4; s++) {
            int fi = tid + s * 256;
            int r = fi >> 4, c = (fi & 15) << 2;
            float4 vv = *reinterpret_cast<const float4*>(gv + base + r * 64 + c);
            Vs[(c + 0) * 68 + r] = vv.x;
            Vs[(c + 1) * 68 + r] = vv.y;
            Vs[(c + 2) * 68 + r] = vv.z;
            Vs[(c + 3) * 68 + r] = vv.w;
        }
        CP_WAIT0();                     // K (and Q on j=0) resident
        __syncthreads();

        // S = Q[128x64] @ K_j[64x64]^T
        float s_acc[2][4][4] = {};
        #pragma unroll
        for (int kc = 0; kc < 8; kc++) {
            const int kb = kc * 8;
            uint32_t af[2][4], bf[4][2];
            #pragma unroll
            for (int mi = 0; mi < 2; mi++) {
                int r = wm + mi * 16 + gid;
                af[mi][0] = __float_as_uint(Qs[ r      * 68 + kb + tig    ]);
                af[mi][1] = __float_as_uint(Qs[(r + 8) * 68 + kb + tig    ]);
                af[mi][2] = __float_as_uint(Qs[ r      * 68 + kb + tig + 4]);
                af[mi][3] = __float_as_uint(Qs[(r + 8) * 68 + kb + tig + 4]);
            }
            #pragma unroll
            for (int ni = 0; ni < 4; ni++) {
                int r = wn + ni * 8 + gid;
                bf[ni][0] = __float_as_uint(Ks[r * 68 + kb + tig    ]);
                bf[ni][1] = __float_as_uint(Ks[r * 68 + kb + tig + 4]);
            }
            #pragma unroll
            for (int mi = 0; mi < 2; mi++)
                #pragma unroll
                for (int ni = 0; ni < 4; ni++)
                    MMA_TF32(s_acc[mi][ni], af[mi][0], af[mi][1], af[mi][2],
                             af[mi][3], bf[ni][0], bf[ni][1]);
        }

        // exp -> P (smem tf32), accumulate rowsums
        #pragma unroll
        for (int mi = 0; mi < 2; mi++) {
            int r0 = wm + mi * 16 + gid;
            #pragma unroll
            for (int ni = 0; ni < 4; ni++) {
                int c = wn + ni * 8 + tig * 2;
                float e0 = __expf(s_acc[mi][ni][0] * 0.125f);
                float e1 = __expf(s_acc[mi][ni][1] * 0.125f);
                float e2 = __expf(s_acc[mi][ni][2] * 0.125f);
                float e3 = __expf(s_acc[mi][ni][3] * 0.125f);
                Ps[ r0      * 68 + c    ] = f2tf(e0);
                Ps[ r0      * 68 + c + 1] = f2tf(e1);
                Ps[(r0 + 8) * 68 + c    ] = f2tf(e2);
                Ps[(r0 + 8) * 68 + c + 1] = f2tf(e3);
                rsum[mi * 2 + 0] += e0 + e1;
                rsum[mi * 2 + 1] += e2 + e3;
            }
        }
        __syncthreads();                // Ps ready

        // ctx += P[128x64] @ V_j  (Vs is [hd][key] -> NT B operand)
        #pragma unroll
        for (int kc = 0; kc < 8; kc++) {
            const int kb = kc * 8;
            uint32_t af[2][4], bf[4][2];
            #pragma unroll
            for (int mi = 0; mi < 2; mi++) {
                int r = wm + mi * 16 + gid;
                af[mi][0] = __float_as_uint(Ps[ r      * 68 + kb + tig    ]);
                af[mi][1] = __float_as_uint(Ps[(r + 8) * 68 + kb + tig    ]);
                af[mi][2] = __float_as_uint(Ps[ r      * 68 + kb + tig + 4]);
                af[mi][3] = __float_as_uint(Ps[(r + 8) * 68 + kb + tig + 4]);
            }
            #pragma unroll
            for (int ni = 0; ni < 4; ni++) {
                int r = wn + ni * 8 + gid;
                bf[ni][0] = __float_as_uint(Vs[r * 68 + kb + tig    ]);
                bf[ni][1] = __float_as_uint(Vs[r * 68 + kb + tig + 4]);
            }
            #pragma unroll
            for (int mi = 0; mi < 2; mi++)
                #pragma unroll
                for (int ni = 0; ni < 4; ni++)
                    MMA_TF32(acc[mi][ni], af[mi][0], af[mi][1], af[mi][2],
                             af[mi][3], bf[ni][0], bf[ni][1]);
        }
    }

    // ---- reduce rowsums ----
    #pragma unroll
    for (int i = 0; i < 4; i++) {
        rsum[i] += __shfl_xor_sync(0xffffffffu, rsum[i], 1);
        rsum[i] += __shfl_xor_sync(0xffffffffu, rsum[i], 2);
    }
    if (tig == 0) {
        #pragma unroll
        for (int i = 0; i < 4; i++) {
            int r = wm + (i >> 1) * 16 + gid + (i & 1) * 8;
            ssum[r * 2 + colg] = rsum[i];
        }
    }
    __syncthreads();
    if (tid < 128) {
        float v = 1.0f / (ssum[tid * 2] + ssum[tid * 2 + 1]);
        sinv[tid] = v;
        ginv[(long)z * 2048 + m0 + tid] = v;
    }
    __syncthreads();

    // ---- write normalized ctx tf32-rounded (consumed by out-proj) ----
    const int b = z >> 4, h = z & 15;
    #pragma unroll
    for (int mi = 0; mi < 2; mi++) {
        int r0 = wm + mi * 16 + gid;
        float s0 = sinv[r0], s1 = sinv[r0 + 8];
        #pragma unroll
        for (int ni = 0; ni < 4; ni++) {
            int c = wn + ni * 8 + tig * 2;
            long base = ((long)(b * 2048 + m0 + r0) << 10) + h * 64 + c;
            *(float2*)(ctx + base) =
                make_float2(f2tf(acc[mi][ni][0] * s0), f2tf(acc[mi][ni][1] * s0));
            *(float2*)(ctx + base + (8L << 10)) =
                make_float2(f2tf(acc[mi][ni][2] * s1), f2tf(acc[mi][ni][3] * s1));
        }
    }
}

// ---------------- tf32 pre-round of the three inputs -------------------------
__global__ void __launch_bounds__(256)
round3(const float* __restrict__ q, const float* __restrict__ k,
       const float* __restrict__ v, float* __restrict__ oq,
       float* __restrict__ ok, float* __restrict__ ov)
{
    const int z = blockIdx.y;
    const float* src = (z == 0) ? q  : (z == 1) ? k  : v;
    float*       dst = (z == 0) ? oq : (z == 1) ? ok : ov;
    long i = (long)blockIdx.x * 256 + threadIdx.x;
    float4 a = reinterpret_cast<const float4*>(src)[i];
    a.x = f2tf(a.x); a.y = f2tf(a.y); a.z = f2tf(a.z); a.w = f2tf(a.w);
    reinterpret_cast<float4*>(dst)[i] = a;
}

// ---------------- fused 4x 1024x1024 weight transpose (tf32 out) -------------
__global__ void __launch_bounds__(256)
transpose4(const float* __restrict__ w0, const float* __restrict__ w1,
           const float* __restrict__ w2, const float* __restrict__ w3,
           float* __restrict__ out)
{
    __shared__ float t[32][33];
    const int z = blockIdx.z;
    const float* in = (z == 0) ? w0 : (z == 1) ? w1 : (z == 2) ? w2 : w3;
    float* o = out + (long)z * 1024 * 1024;
    int tx = threadIdx.x, ty = threadIdx.y;
    int x  = blockIdx.x * 32 + tx;
    #pragma unroll
    for (int i = ty; i < 32; i += 8)
        t[i][tx] = in[(long)(blockIdx.y * 32 + i) * 1024 + x];
    __syncthreads();
    int xo = blockIdx.y * 32 + tx;
    #pragma unroll
    for (int i = ty; i < 32; i += 8)
        o[(long)(blockIdx.x * 32 + i) * 1024 + xo] = f2tf(t[tx][i]);
}

// ---------------- launch ------------------------------------------------------
extern "C" void kernel_launch(void* const* d_in, const int* in_sizes, int n_in,
                              void* d_out, int out_size)
{
    const float* query = (const float*)d_in[0];
    const float* key   = (const float*)d_in[1];
    const float* value = (const float*)d_in[2];
    const float* Wq    = (const float*)d_in[3];
    const float* bq    = (const float*)d_in[4];
    const float* Wk    = (const float*)d_in[5];
    const float* bk    = (const float*)d_in[6];
    const float* Wv    = (const float*)d_in[7];
    const float* bv    = (const float*)d_in[8];
    const float* Wo    = (const float*)d_in[9];
    const float* bo    = (const float*)d_in[10];

    float* out  = (float*)d_out;
    float* attn = out + BSD;             // outputs concatenated: (out, attn)

    void* p;
    cudaGetSymbolAddress(&p, g_wt);  float* wt   = (float*)p;
    cudaGetSymbolAddress(&p, g_qr);  float* qr   = (float*)p;
    cudaGetSymbolAddress(&p, g_kr);  float* kr   = (float*)p;
    cudaGetSymbolAddress(&p, g_vr);  float* vr   = (float*)p;
    cudaGetSymbolAddress(&p, g_q);   float* qh   = (float*)p;
    cudaGetSymbolAddress(&p, g_k);   float* kh   = (float*)p;
    cudaGetSymbolAddress(&p, g_v);   float* vh   = (float*)p;
    cudaGetSymbolAddress(&p, g_ctx); float* ctx  = (float*)p;
    cudaGetSymbolAddress(&p, g_inv); float* vinv = (float*)p;

    const int FLASH_SMEM =
        (128*68 + 64*68 + 64*68 + 128*68 + 256 + 128) * 4;   // 105984 B
    static int smem_set = 0;
    if (!smem_set) {
        cudaFuncSetAttribute(flash_ctx,
                             cudaFuncAttributeMaxDynamicSharedMemorySize,
                             FLASH_SMEM);
        cudaFuncSetAttribute(qkv_proj,
                             cudaFuncAttributeMaxDynamicSharedMemorySize,
                             GEMM_SMEMB);
        cudaFuncSetAttribute(attn_out_combo,
                             cudaFuncAttributeMaxDynamicSharedMemorySize,
                             GEMM_SMEMB);
        smem_set = 1;
    }

    const long WS = 1024L * 1024L;

    // 1) tf32-round the three inputs
    round3<<<dim3(4096, 3), 256>>>(query, key, value, qr, kr, vr);

    // 2) all four weight transposes (tf32 out)
    transpose4<<<dim3(32, 32, 4), dim3(32, 8)>>>(Wq, Wk, Wv, Wo, wt);

    // 3) fused Q/K/V projections (cp.async staging, 64x64 warp tiles)
    qkv_proj<<<dim3(4, 32, 3), 256, GEMM_SMEMB>>>(qr, kr, vr, wt,
                                                  bq, bk, bv, qh, kh, vh);

    // 4) fused scores->softmax-sum->ctx; 128-q tiles, 2 CTAs/SM
    flash_ctx<<<dim3(1, 16, BH), 256, FLASH_SMEM>>>(qh, kh, vh, ctx, vinv);

    // 5) merged: out-projection (first) + normalized attn write
    attn_out_combo<<<128 + 4096, 256, GEMM_SMEMB>>>(qh, kh, vinv, attn,
                                                    ctx, wt + 3 * WS, bo, out);
}

// round 17
// speedup vs baseline: 1.2302x; 1.0955x over previous
#include <cuda_runtime.h>
#include <cstdint>

// Problem constants (fixed by the reference)
#define B_  2
#define S_  2048
#define D_  1024
#define H_  16
#define HD_ 64
#define BH  (B_*H_)            // 32
#define BSD ((long)B_*S_*D_)   // 4194304

// ---------------- scratch (static device globals; no allocation) ------------
__device__ float g_wt [4u*1024u*1024u];   // transposed weights [4][n][k] (tf32)
__device__ float g_qr [BSD];              // tf32-rounded query
__device__ float g_kr [BSD];              // tf32-rounded key
__device__ float g_vr [BSD];              // tf32-rounded value
__device__ float g_q  [BH * S_ * HD_];    // [b,h,s,hd] (tf32)
__device__ float g_k  [BH * S_ * HD_];    // [b,h,s,hd] (tf32)
__device__ float g_v  [BH * S_ * HD_];    // [b,h,s,hd] (tf32)
__device__ float g_ctx[B_ * S_ * D_];     // [b,s,d] (tf32)
__device__ float g_inv[BH * S_];          // 1 / softmax rowsum (f32)

// ---------------- helpers ---------------------------------------------------
__device__ __forceinline__ float f2tf(float f) {
    uint32_t u;
    asm("cvt.rna.tf32.f32 %0, %1;" : "=r"(u) : "f"(f));
    return __uint_as_float(u);
}

__device__ __forceinline__ uint32_t smem_u32(const void* p) {
    uint32_t a;
    asm("{ .reg .u64 t; cvta.to.shared.u64 t, %1; cvt.u32.u64 %0, t; }"
        : "=r"(a) : "l"(p));
    return a;
}

__device__ __forceinline__ void cp16(uint32_t dst, const float* src) {
    asm volatile("cp.async.cg.shared.global [%0], [%1], 16;\n"
                 :: "r"(dst), "l"(src));
}

#define CP_COMMIT() asm volatile("cp.async.commit_group;\n" ::: "memory")
#define CP_WAIT0()  asm volatile("cp.async.wait_group 0;\n" ::: "memory")
#define CP_WAIT1()  asm volatile("cp.async.wait_group 1;\n" ::: "memory")

#define MMA_TF32(d, a0, a1, a2, a3, b0, b1)                                   \
    asm volatile(                                                             \
        "mma.sync.aligned.m16n8k8.row.col.f32.tf32.tf32.f32 "                 \
        "{%0,%1,%2,%3}, {%4,%5,%6,%7}, {%8,%9}, {%0,%1,%2,%3};\n"             \
        : "+f"((d)[0]), "+f"((d)[1]), "+f"((d)[2]), "+f"((d)[3])              \
        : "r"(a0), "r"(a1), "r"(a2), "r"(a3), "r"(b0), "r"(b1))

// ---------------- TF32 NT GEMM body: 128x256 tile, 8 warps of 64x64 ----------
// Operands must already be tf32-rounded in gmem; staging is cp.async.cg.
constexpr int SMA = 128 * 20;
constexpr int SMB = 256 * 20;
constexpr int GEMM_SMF = 2 * SMA + 2 * SMB + 128;
constexpr int GEMM_SMEMB = GEMM_SMF * 4;

template<int EPI>
__device__ __forceinline__ void gemm_body(
    float* sm_, const float* __restrict__ Ab, const float* __restrict__ Bb,
    const float* __restrict__ bias, float* __restrict__ C,
    const float* __restrict__ inv, int z, int m0, int n0, int K)
{
    float* sinv = sm_ + 2 * SMA + 2 * SMB;
    const uint32_t sb = smem_u32(sm_);

    const int tid  = threadIdx.x;
    const int lr = tid >> 2;
    const int lc = (tid & 3) << 2;
    const int warp = tid >> 5;
    const int lane = tid & 31;
    const int wm  = (warp >> 2) * 64;
    const int wn  = (warp & 3) * 64;
    const int gid = lane >> 2;
    const int tig = lane & 3;

    auto issue = [&](int kt, int buf) {
        const int k0 = kt * 16;
        const uint32_t ab = sb + (buf * SMA) * 4;
        const uint32_t bbs = sb + (2 * SMA + buf * SMB) * 4;
        #pragma unroll
        for (int i = 0; i < 2; i++) {
            int r = lr + i * 64;
            cp16(ab + (r * 20 + lc) * 4, Ab + (long)(m0 + r) * K + k0 + lc);
        }
        #pragma unroll
        for (int i = 0; i < 4; i++) {
            int r = lr + i * 64;
            cp16(bbs + (r * 20 + lc) * 4, Bb + (long)(n0 + r) * K + k0 + lc);
        }
        CP_COMMIT();
    };

    float acc[4][8][4] = {};
    auto compute = [&](int buf) {
        const float* Asb = sm_ + buf * SMA;
        const float* Bsb = sm_ + 2 * SMA + buf * SMB;
        #pragma unroll
        for (int kk = 0; kk < 2; kk++) {
            const int kb = kk * 8;
            uint32_t af[4][4], bf[8][2];
            #pragma unroll
            for (int mi = 0; mi < 4; mi++) {
                int r = wm + mi * 16 + gid;
                af[mi][0] = __float_as_uint(Asb[ r      * 20 + kb + tig    ]);
                af[mi][1] = __float_as_uint(Asb[(r + 8) * 20 + kb + tig    ]);
                af[mi][2] = __float_as_uint(Asb[ r      * 20 + kb + tig + 4]);
                af[mi][3] = __float_as_uint(Asb[(r + 8) * 20 + kb + tig + 4]);
            }
            #pragma unroll
            for (int ni = 0; ni < 8; ni++) {
                int r = wn + ni * 8 + gid;
                bf[ni][0] = __float_as_uint(Bsb[r * 20 + kb + tig    ]);
                bf[ni][1] = __float_as_uint(Bsb[r * 20 + kb + tig + 4]);
            }
            #pragma unroll
            for (int mi = 0; mi < 4; mi++)
                #pragma unroll
                for (int ni = 0; ni < 8; ni++)
                    MMA_TF32(acc[mi][ni], af[mi][0], af[mi][1], af[mi][2],
                             af[mi][3], bf[ni][0], bf[ni][1]);
        }
    };

    if (EPI == 2 && tid < 128)
        sinv[tid] = inv[(long)z * 2048 + m0 + tid];

    const int NT = K >> 4;
    issue(0, 0);
    int buf = 0;
    for (int kt = 0; kt < NT; kt++) {
        CP_WAIT0();
        __syncthreads();
        if (kt + 1 < NT) issue(kt + 1, buf ^ 1);
        compute(buf);
        buf ^= 1;
    }

    #pragma unroll
    for (int mi = 0; mi < 4; mi++) {
        #pragma unroll
        for (int ni = 0; ni < 8; ni++) {
            int lrow = wm + mi * 16 + gid;
            int m = m0 + lrow;
            int n = n0 + wn + ni * 8 + tig * 2;
            float a0 = acc[mi][ni][0], a1 = acc[mi][ni][1];
            float a2 = acc[mi][ni][2], a3 = acc[mi][ni][3];
            if constexpr (EPI == 0) {
                int b = m >> 11, s = m & 2047, h = n >> 6, hd = n & 63;
                long base = (long)((b * 16 + h) * 2048 + s) * 64 + hd;
                float b0 = bias[n], b1 = bias[n + 1];
                *(float2*)(C + base)       = make_float2(f2tf(a0 + b0), f2tf(a1 + b1));
                *(float2*)(C + base + 512) = make_float2(f2tf(a2 + b0), f2tf(a3 + b1));
            } else if constexpr (EPI == 2) {
                float s0 = sinv[lrow], s1 = sinv[lrow + 8];
                float e0 = __expf(a0 * 0.125f) * s0;
                float e1 = __expf(a1 * 0.125f) * s0;
                float e2 = __expf(a2 * 0.125f) * s1;
                float e3 = __expf(a3 * 0.125f) * s1;
                long base = (long)z * (2048L * 2048) + (long)m * 2048 + n;
                __stcs((float2*)(C + base),            make_float2(e0, e1));
                __stcs((float2*)(C + base + 8 * 2048), make_float2(e2, e3));
            } else {
                long base = (long)m * 1024 + n;
                float b0 = bias[n], b1 = bias[n + 1];
                *(float2*)(C + base)            = make_float2(a0 + b0, a1 + b1);
                *(float2*)(C + base + 8 * 1024) = make_float2(a2 + b0, a3 + b1);
            }
        }
    }
}

// ---------------- fused Q/K/V projection (grid.z selects) --------------------
__global__ void __launch_bounds__(256)
qkv_proj(const float* __restrict__ q, const float* __restrict__ k,
         const float* __restrict__ v, const float* __restrict__ wt,
         const float* __restrict__ bq, const float* __restrict__ bk,
         const float* __restrict__ bv,
         float* __restrict__ gq, float* __restrict__ gk, float* __restrict__ gv)
{
    extern __shared__ float sm_[];
    const int z = blockIdx.z;
    const float* A    = (z == 0) ? q  : (z == 1) ? k  : v;
    const float* bias = (z == 0) ? bq : (z == 1) ? bk : bv;
    float*       C    = (z == 0) ? gq : (z == 1) ? gk : gv;
    gemm_body<0>(sm_, A, wt + (long)z * 1024 * 1024, bias, C, nullptr, 0,
                 blockIdx.y * 128, blockIdx.x * 256, 1024);
}

// ---------------- merged pass2 (attn write) + output projection --------------
__global__ void __launch_bounds__(256)
attn_out_combo(const float* __restrict__ qh, const float* __restrict__ kh,
               const float* __restrict__ vinv, float* __restrict__ attn,
               const float* __restrict__ ctx, const float* __restrict__ wo_t,
               const float* __restrict__ bo, float* __restrict__ out)
{
    extern __shared__ float sm_[];
    const int bid = blockIdx.x;
    if (bid < 128) {
        int m0 = (bid >> 2) * 128;
        int n0 = (bid & 3) * 256;
        gemm_body<4>(sm_, ctx, wo_t, bo, out, nullptr, 0, m0, n0, 1024);
    } else {
        int t  = bid - 128;
        int z  = t >> 7;
        int m0 = ((t >> 3) & 15) * 128;
        int n0 = (t & 7) * 256;
        gemm_body<2>(sm_, qh + (long)z * S_ * HD_, kh + (long)z * S_ * HD_,
                     nullptr, attn, vinv, z, m0, n0, 64);
    }
}

// ---------------- flash pass1: 128-q tile, pipelined cp.async K/V ------------
// 8 warps of 32x32, 2 CTAs/SM. V staged ROW-MAJOR [key][hd] at stride 72 via
// cp.async (conflict-free PV fragment loads at banks 8*tig+gid; no transpose
// STS, no V LDG). K/V loads software-pipelined in single buffers with
// interleaved commit groups: K(j+1) issued after the post-exp barrier
// (hidden under PV(j)), V(j+1) after the post-PV barrier (hidden under
// S(j+1)); wait_group 1 at loop top retires K, wait_group 0 pre-PV retires V.
// Math order per row identical to R16 -> bit-identical results.
__global__ void __launch_bounds__(256, 2)
flash_ctx(const float* __restrict__ gq, const float* __restrict__ gk,
          const float* __restrict__ gv, float* __restrict__ ctx,
          float* __restrict__ ginv)
{
    extern __shared__ float sm[];
    float* Qs   = sm;                   // 128*68 = 8704
    float* Ks   = Qs + 128 * 68;        // 64*68  = 4352
    float* Vs   = Ks + 64 * 68;         // 64*72  = 4608  ([key][hd], stride 72)
    float* Ps   = Vs + 64 * 72;         // 128*68 = 8704
    float* ssum = Ps + 128 * 68;        // 256
    float* sinv = ssum + 256;           // 128    -> total 26752 floats ~107KB

    const uint32_t sb = smem_u32(sm);
    const uint32_t KOF = 128 * 68;
    const uint32_t VOF = KOF + 64 * 68;
    const int tid  = threadIdx.x;
    const int z    = blockIdx.z;
    const int m0   = blockIdx.y * 128;
    const int warp = tid >> 5, lane = tid & 31;
    const int wm   = (warp >> 1) * 32;
    const int wn   = (warp & 1) * 32;
    const int colg = warp & 1;
    const int gid  = lane >> 2, tig = lane & 3;

    const int lr = tid >> 4;            // 0..15 (row step for 64-row tiles)
    const int lc = (tid & 15) << 2;     // 0..60

    auto issueK = [&](int j) {
        const float* src = gk + ((long)z * 2048 + j * 64) * 64;
        #pragma unroll
        for (int s = 0; s < 4; s++) {
            int r = lr + s * 16;
            cp16(sb + (KOF + r * 68 + lc) * 4, src + r * 64 + lc);
        }
        CP_COMMIT();
    };
    auto issueV = [&](int j) {
        const float* src = gv + ((long)z * 2048 + j * 64) * 64;
        #pragma unroll
        for (int s = 0; s < 4; s++) {
            int r = lr + s * 16;
            cp16(sb + (VOF + r * 72 + lc) * 4, src + r * 64 + lc);
        }
        CP_COMMIT();
    };

    // prologue: group A = Q + K(0); group B = V(0)
    {
        const float* q = gq + ((long)z * 2048 + m0) * 64;
        #pragma unroll
        for (int s = 0; s < 8; s++) {
            int fi = tid + s * 256;
            int r = fi >> 4, c = (fi & 15) << 2;
            cp16(sb + (r * 68 + c) * 4, q + r * 64 + c);
        }
        const float* ksrc = gk + ((long)z * 2048) * 64;
        #pragma unroll
        for (int s = 0; s < 4; s++) {
            int r = lr + s * 16;
            cp16(sb + (KOF + r * 68 + lc) * 4, ksrc + r * 64 + lc);
        }
        CP_COMMIT();
    }
    issueV(0);

    float acc[2][4][4] = {};
    float rsum[4] = {0.f, 0.f, 0.f, 0.f};

    for (int j = 0; j < 32; j++) {
        CP_WAIT1();                     // K(j) (+Q on j=0) resident
        __syncthreads();                // visible to all; prev PV done w/ Ks? (no Ks reads in PV)

        // S = Q[128x64] @ K_j[64x64]^T
        float s_acc[2][4][4] = {};
        #pragma unroll
        for (int kc = 0; kc < 8; kc++) {
            const int kb = kc * 8;
            uint32_t af[2][4], bf[4][2];
            #pragma unroll
            for (int mi = 0; mi < 2; mi++) {
                int r = wm + mi * 16 + gid;
                af[mi][0] = __float_as_uint(Qs[ r      * 68 + kb + tig    ]);
                af[mi][1] = __float_as_uint(Qs[(r + 8) * 68 + kb + tig    ]);
                af[mi][2] = __float_as_uint(Qs[ r      * 68 + kb + tig + 4]);
                af[mi][3] = __float_as_uint(Qs[(r + 8) * 68 + kb + tig + 4]);
            }
            #pragma unroll
            for (int ni = 0; ni < 4; ni++) {
                int r = wn + ni * 8 + gid;
                bf[ni][0] = __float_as_uint(Ks[r * 68 + kb + tig    ]);
                bf[ni][1] = __float_as_uint(Ks[r * 68 + kb + tig + 4]);
            }
            #pragma unroll
            for (int mi = 0; mi < 2; mi++)
                #pragma unroll
                for (int ni = 0; ni < 4; ni++)
                    MMA_TF32(s_acc[mi][ni], af[mi][0], af[mi][1], af[mi][2],
                             af[mi][3], bf[ni][0], bf[ni][1]);
        }

        // exp -> P (smem tf32), accumulate rowsums
        #pragma unroll
        for (int mi = 0; mi < 2; mi++) {
            int r0 = wm + mi * 16 + gid;
            #pragma unroll
            for (int ni = 0; ni < 4; ni++) {
                int c = wn + ni * 8 + tig * 2;
                float e0 = __expf(s_acc[mi][ni][0] * 0.125f);
                float e1 = __expf(s_acc[mi][ni][1] * 0.125f);
                float e2 = __expf(s_acc[mi][ni][2] * 0.125f);
                float e3 = __expf(s_acc[mi][ni][3] * 0.125f);
                Ps[ r0      * 68 + c    ] = f2tf(e0);
                Ps[ r0      * 68 + c + 1] = f2tf(e1);
                Ps[(r0 + 8) * 68 + c    ] = f2tf(e2);
                Ps[(r0 + 8) * 68 + c + 1] = f2tf(e3);
                rsum[mi * 2 + 0] += e0 + e1;
                rsum[mi * 2 + 1] += e2 + e3;
            }
        }
        CP_WAIT0();                     // V(j) resident (only group left)
        __syncthreads();                // Ps ready + V visible; S reads of Ks done

        if (j < 31) issueK(j + 1);      // overwrite Ks; hidden under PV

        // ctx += P[128x64] @ V_j   (Vs row-major [key][hd], stride 72)
        #pragma unroll
        for (int kc = 0; kc < 8; kc++) {
            const int kb = kc * 8;
            uint32_t af[2][4], bf[4][2];
            #pragma unroll
            for (int mi = 0; mi < 2; mi++) {
                int r = wm + mi * 16 + gid;
                af[mi][0] = __float_as_uint(Ps[ r      * 68 + kb + tig    ]);
                af[mi][1] = __float_as_uint(Ps[(r + 8) * 68 + kb + tig    ]);
                af[mi][2] = __float_as_uint(Ps[ r      * 68 + kb + tig + 4]);
                af[mi][3] = __float_as_uint(Ps[(r + 8) * 68 + kb + tig + 4]);
            }
            #pragma unroll
            for (int ni = 0; ni < 4; ni++) {
                int r = wn + ni * 8 + gid;             // hd index
                bf[ni][0] = __float_as_uint(Vs[(kb + tig)     * 72 + r]);
                bf[ni][1] = __float_as_uint(Vs[(kb + tig + 4) * 72 + r]);
            }
            #pragma unroll
            for (int mi = 0; mi < 2; mi++)
                #pragma unroll
                for (int ni = 0; ni < 4; ni++)
                    MMA_TF32(acc[mi][ni], af[mi][0], af[mi][1], af[mi][2],
                             af[mi][3], bf[ni][0], bf[ni][1]);
        }
        __syncthreads();                // all PV reads of Vs done
        if (j < 31) issueV(j + 1);      // overwrite Vs; hidden under next S
    }

    // ---- reduce rowsums ----
    #pragma unroll
    for (int i = 0; i < 4; i++) {
        rsum[i] += __shfl_xor_sync(0xffffffffu, rsum[i], 1);
        rsum[i] += __shfl_xor_sync(0xffffffffu, rsum[i], 2);
    }
    if (tig == 0) {
        #pragma unroll
        for (int i = 0; i < 4; i++) {
            int r = wm + (i >> 1) * 16 + gid + (i & 1) * 8;
            ssum[r * 2 + colg] = rsum[i];
        }
    }
    __syncthreads();
    if (tid < 128) {
        float v = 1.0f / (ssum[tid * 2] + ssum[tid * 2 + 1]);
        sinv[tid] = v;
        ginv[(long)z * 2048 + m0 + tid] = v;
    }
    __syncthreads();

    // ---- write normalized ctx tf32-rounded (consumed by out-proj) ----
    const int b = z >> 4, h = z & 15;
    #pragma unroll
    for (int mi = 0; mi < 2; mi++) {
        int r0 = wm + mi * 16 + gid;
        float s0 = sinv[r0], s1 = sinv[r0 + 8];
        #pragma unroll
        for (int ni = 0; ni < 4; ni++) {
            int c = wn + ni * 8 + tig * 2;
            long base = ((long)(b * 2048 + m0 + r0) << 10) + h * 64 + c;
            *(float2*)(ctx + base) =
                make_float2(f2tf(acc[mi][ni][0] * s0), f2tf(acc[mi][ni][1] * s0));
            *(float2*)(ctx + base + (8L << 10)) =
                make_float2(f2tf(acc[mi][ni][2] * s1), f2tf(acc[mi][ni][3] * s1));
        }
    }
}

// ---------------- tf32 pre-round of the three inputs -------------------------
__global__ void __launch_bounds__(256)
round3(const float* __restrict__ q, const float* __restrict__ k,
       const float* __restrict__ v, float* __restrict__ oq,
       float* __restrict__ ok, float* __restrict__ ov)
{
    const int z = blockIdx.y;
    const float* src = (z == 0) ? q  : (z == 1) ? k  : v;
    float*       dst = (z == 0) ? oq : (z == 1) ? ok : ov;
    long i = (long)blockIdx.x * 256 + threadIdx.x;
    float4 a = reinterpret_cast<const float4*>(src)[i];
    a.x = f2tf(a.x); a.y = f2tf(a.y); a.z = f2tf(a.z); a.w = f2tf(a.w);
    reinterpret_cast<float4*>(dst)[i] = a;
}

// ---------------- fused 4x 1024x1024 weight transpose (tf32 out) -------------
__global__ void __launch_bounds__(256)
transpose4(const float* __restrict__ w0, const float* __restrict__ w1,
           const float* __restrict__ w2, const float* __restrict__ w3,
           float* __restrict__ out)
{
    __shared__ float t[32][33];
    const int z = blockIdx.z;
    const float* in = (z == 0) ? w0 : (z == 1) ? w1 : (z == 2) ? w2 : w3;
    float* o = out + (long)z * 1024 * 1024;
    int tx = threadIdx.x, ty = threadIdx.y;
    int x  = blockIdx.x * 32 + tx;
    #pragma unroll
    for (int i = ty; i < 32; i += 8)
        t[i][tx] = in[(long)(blockIdx.y * 32 + i) * 1024 + x];
    __syncthreads();
    int xo = blockIdx.y * 32 + tx;
    #pragma unroll
    for (int i = ty; i < 32; i += 8)
        o[(long)(blockIdx.x * 32 + i) * 1024 + xo] = f2tf(t[tx][i]);
}

// ---------------- launch ------------------------------------------------------
extern "C" void kernel_launch(void* const* d_in, const int* in_sizes, int n_in,
                              void* d_out, int out_size)
{
    const float* query = (const float*)d_in[0];
    const float* key   = (const float*)d_in[1];
    const float* value = (const float*)d_in[2];
    const float* Wq    = (const float*)d_in[3];
    const float* bq    = (const float*)d_in[4];
    const float* Wk    = (const float*)d_in[5];
    const float* bk    = (const float*)d_in[6];
    const float* Wv    = (const float*)d_in[7];
    const float* bv    = (const float*)d_in[8];
    const float* Wo    = (const float*)d_in[9];
    const float* bo    = (const float*)d_in[10];

    float* out  = (float*)d_out;
    float* attn = out + BSD;             // outputs concatenated: (out, attn)

    void* p;
    cudaGetSymbolAddress(&p, g_wt);  float* wt   = (float*)p;
    cudaGetSymbolAddress(&p, g_qr);  float* qr   = (float*)p;
    cudaGetSymbolAddress(&p, g_kr);  float* kr   = (float*)p;
    cudaGetSymbolAddress(&p, g_vr);  float* vr   = (float*)p;
    cudaGetSymbolAddress(&p, g_q);   float* qh   = (float*)p;
    cudaGetSymbolAddress(&p, g_k);   float* kh   = (float*)p;
    cudaGetSymbolAddress(&p, g_v);   float* vh   = (float*)p;
    cudaGetSymbolAddress(&p, g_ctx); float* ctx  = (float*)p;
    cudaGetSymbolAddress(&p, g_inv); float* vinv = (float*)p;

    const int FLASH_SMEM =
        (128*68 + 64*68 + 64*72 + 128*68 + 256 + 128) * 4;   // 107008 B
    static int smem_set = 0;
    if (!smem_set) {
        cudaFuncSetAttribute(flash_ctx,
                             cudaFuncAttributeMaxDynamicSharedMemorySize,
                             FLASH_SMEM);
        cudaFuncSetAttribute(qkv_proj,
                             cudaFuncAttributeMaxDynamicSharedMemorySize,
                             GEMM_SMEMB);
        cudaFuncSetAttribute(attn_out_combo,
                             cudaFuncAttributeMaxDynamicSharedMemorySize,
                             GEMM_SMEMB);
        smem_set = 1;
    }

    const long WS = 1024L * 1024L;

    // 1) tf32-round the three inputs
    round3<<<dim3(4096, 3), 256>>>(query, key, value, qr, kr, vr);

    // 2) all four weight transposes (tf32 out)
    transpose4<<<dim3(32, 32, 4), dim3(32, 8)>>>(Wq, Wk, Wv, Wo, wt);

    // 3) fused Q/K/V projections (cp.async staging, 64x64 warp tiles)
    qkv_proj<<<dim3(4, 32, 3), 256, GEMM_SMEMB>>>(qr, kr, vr, wt,
                                                  bq, bk, bv, qh, kh, vh);

    // 4) fused scores->softmax-sum->ctx; pipelined cp.async K/V, 2 CTAs/SM
    flash_ctx<<<dim3(1, 16, BH), 256, FLASH_SMEM>>>(qh, kh, vh, ctx, vinv);

    // 5) merged: out-projection (first) + normalized attn write
    attn_out_combo<<<128 + 4096, 256, GEMM_SMEMB>>>(qh, kh, vinv, attn,
                                                    ctx, wt + 3 * WS, bo, out);
}